// round 8
// baseline (speedup 1.0000x reference)
#include <cuda_runtime.h>
#include <cstdint>

#define WID 256
#define HGT 256
#define HW  65536
#define BATCH 8
#define BHW 524288

// ---------------- scratch ----------------
__device__ float g_vs[BHW];                        // V/sf
__device__ float g_actA[(size_t)BATCH * HW * 32];  // NHWC-permuted producer layout (plain NHWC)
__device__ float g_actB[(size_t)BATCH * HW * 64];
__device__ float g_w2p[9 * 4 * 32 * 20];           // conv2 weights, lane-packed, tf32
__device__ float g_w3p[9 * 8 * 32 * 12];           // conv3 weights, lane-packed, tf32

// ---------------- helpers ----------------
__device__ __forceinline__ float rna_tf32(float x) {
    uint32_t u;
    asm("cvt.rna.tf32.f32 %0, %1;" : "=r"(u) : "f"(x));
    return __uint_as_float(u);
}
__device__ __forceinline__ uint32_t fau(float x) { return __float_as_uint(x); }

#define MMA_TF32(d, a, b0, b1) \
    asm volatile("mma.sync.aligned.m16n8k8.row.col.f32.tf32.tf32.f32 " \
        "{%0,%1,%2,%3}, {%4,%5,%6,%7}, {%8,%9}, {%0,%1,%2,%3};" \
        : "+f"((d)[0]), "+f"((d)[1]), "+f"((d)[2]), "+f"((d)[3]) \
        : "r"((a)[0]), "r"((a)[1]), "r"((a)[2]), "r"((a)[3]), "r"(b0), "r"(b1))

// ---------------- prep ----------------
__global__ void __launch_bounds__(256) prep_kernel(
    const float* __restrict__ inp, const float* __restrict__ H0,
    const float* __restrict__ C0, const float* __restrict__ c2,
    const float* __restrict__ sf, float* __restrict__ out,
    float* __restrict__ vs)
{
    int idx = blockIdx.x * 256 + threadIdx.x;
    if (idx >= BHW) return;
    int b = idx >> 16, rem = idx & 65535, y = rem >> 8, x = rem & 255;

    float c  = inp[idx];
    float up = (y > 0)       ? inp[idx - WID] : 0.f;
    float dn = (y < HGT - 1) ? inp[idx + WID] : 0.f;
    float lf = (x > 0)       ? inp[idx - 1]   : 0.f;
    float rt = (x < WID - 1) ? inp[idx + 1]   : 0.f;
    float lap = up + dn + lf + rt - 4.f * c;

    float c0v = C0[(size_t)b * 2 * HW + rem];
    float Hv  = 2.f * c - c0v + c2[0] * lap;
    float V   = c - H0[idx];

    out[(size_t)BHW + idx]     = Hv;
    out[4 * (size_t)BHW + idx] = V;
    out[2 * (size_t)BHW + (size_t)b * 2 * HW + rem]      = c;
    out[2 * (size_t)BHW + (size_t)b * 2 * HW + HW + rem] = c0v;
    vs[idx] = V / sf[0];
}

// ---------------- weight pack: lane-fragment order, tf32 ----------------
// conv2 used elems: 9*4*32*16; conv3: 9*8*32*8 (both 18432)
__global__ void __launch_bounds__(256) w_pack_k(
    const float* __restrict__ w2, const float* __restrict__ w3,
    float* __restrict__ p2, float* __restrict__ p3)
{
    int idx = blockIdx.x * 256 + threadIdx.x;   // < 18432
    {   // conv2
        int e = idx & 3, j = (idx >> 2) & 3, lane = (idx >> 4) & 31;
        int kk = (idx >> 9) & 3, tap = idx >> 11;
        int qid = lane >> 2, tig = lane & 3;
        int nt = 2 * j + (e >> 1);
        int k = kk * 8 + tig + (e & 1) * 4;
        int n = nt * 8 + qid;
        p2[((tap * 4 + kk) * 32 + lane) * 20 + j * 4 + e] =
            rna_tf32(w2[((size_t)n * 32 + k) * 9 + tap]);
    }
    {   // conv3
        int e = idx & 3, j = (idx >> 2) & 1, lane = (idx >> 3) & 31;
        int kk = (idx >> 8) & 7, tap = idx >> 11;
        int qid = lane >> 2, tig = lane & 3;
        int nt = 2 * j + (e >> 1);
        int k = kk * 8 + tig + (e & 1) * 4;
        int n = nt * 8 + qid;
        p3[((tap * 8 + kk) * 32 + lane) * 12 + j * 4 + e] =
            rna_tf32(w3[((size_t)n * 64 + k) * 9 + tap]);
    }
}

// ---------------- conv1: 1->32 fp32, NHWC out, tf32-rounded ----------------
__global__ void __launch_bounds__(256) conv1_k(
    const float* __restrict__ vs, const float* __restrict__ w,
    const float* __restrict__ bb, float* __restrict__ outp)
{
    __shared__ float sw[288];
    __shared__ float sb[32];
    int tid = threadIdx.x;
    for (int i = tid; i < 288; i += 256) sw[i] = w[i];
    if (tid < 32) sb[tid] = bb[tid];
    __syncthreads();

    int pix = blockIdx.x * 256 + tid;
    int b = pix >> 16, rem = pix & 65535, y = rem >> 8, x = rem & 255;
    float xv[9];
    #pragma unroll
    for (int t = 0; t < 9; t++) {
        int gy = y + t / 3 - 1, gx = x + t % 3 - 1;
        xv[t] = ((unsigned)gy < HGT && (unsigned)gx < WID)
                    ? vs[(b << 16) + (gy << 8) + gx] : 0.f;
    }
    float* op = outp + (size_t)pix * 32;
    #pragma unroll
    for (int c4 = 0; c4 < 8; c4++) {
        float4 o;
        float* po = (float*)&o;
        #pragma unroll
        for (int u = 0; u < 4; u++) {
            int co = c4 * 4 + u;
            float acc = sb[co];
            #pragma unroll
            for (int t = 0; t < 9; t++) acc = fmaf(xv[t], sw[co * 9 + t], acc);
            po[u] = rna_tf32(fmaxf(acc, 0.f));
        }
        *(float4*)(op + c4 * 4) = o;
    }
}

// ---------------- conv2: 32->64 tf32 mma, vectorized fragments ----------------
// CTA 512 thr, tile 16x32. act smem ch-permuted p(ch)=(ch%4)*8+ch/4, AS=36.
__global__ void __launch_bounds__(512, 1) conv2_mma(
    const float* __restrict__ in, const float* __restrict__ wp,
    const float* __restrict__ bias, float* __restrict__ outp)
{
    constexpr int AS = 36;
    extern __shared__ float sm[];
    float* s_act = sm;              // 612*36
    float* s_w   = sm + 22032;      // 23040

    const int tid = threadIdx.x;
    const int b   = blockIdx.z;
    const int x0  = blockIdx.x * 32;
    const int y0  = blockIdx.y * 16;

    const float* inb = in + (size_t)b * HW * 32;
    for (int i = tid; i < 612 * 8; i += 512) {
        int px = i >> 3, j = i & 7;
        int yy = px / 34, xx = px - yy * 34;
        int gy = y0 - 1 + yy, gx = x0 - 1 + xx;
        float4 v = {0.f, 0.f, 0.f, 0.f};
        if ((unsigned)gy < HGT && (unsigned)gx < WID)
            v = *(const float4*)(inb + (size_t)(gy * WID + gx) * 32 + j * 4);
        float* sp = s_act + px * AS;
        sp[j] = v.x; sp[8 + j] = v.y; sp[16 + j] = v.z; sp[24 + j] = v.w;
    }
    for (int e = tid * 4; e < 23040; e += 2048)
        *(float4*)(s_w + e) = *(const float4*)(wp + e);
    __syncthreads();

    const int warp = tid >> 5, lane = tid & 31;
    const int qid  = lane >> 2, tig = lane & 3;

    float acc[2][8][4];
    #pragma unroll
    for (int mt = 0; mt < 2; mt++)
        #pragma unroll
        for (int nt = 0; nt < 8; nt++)
            #pragma unroll
            for (int u = 0; u < 4; u++) acc[mt][nt][u] = 0.f;

    #pragma unroll 1
    for (int tap = 0; tap < 9; tap++) {
        const int base_px = (warp + tap / 3) * 34 + tap % 3;
        uint32_t Ar[4][8];
        #pragma unroll
        for (int r = 0; r < 4; r++) {
            const float4* ap = (const float4*)(s_act + (base_px + qid + r * 8) * AS + tig * 8);
            float4 v0 = ap[0], v1 = ap[1];
            Ar[r][0] = fau(v0.x); Ar[r][1] = fau(v0.y); Ar[r][2] = fau(v0.z); Ar[r][3] = fau(v0.w);
            Ar[r][4] = fau(v1.x); Ar[r][5] = fau(v1.y); Ar[r][6] = fau(v1.z); Ar[r][7] = fau(v1.w);
        }
        #pragma unroll
        for (int kk = 0; kk < 4; kk++) {
            const float4* bp = (const float4*)(s_w + ((tap * 4 + kk) * 32 + lane) * 20);
            float4 bf[4] = {bp[0], bp[1], bp[2], bp[3]};
            const float* fb = (const float*)bf;
            uint32_t aF[2][4];
            #pragma unroll
            for (int mt = 0; mt < 2; mt++) {
                aF[mt][0] = Ar[2 * mt][2 * kk];
                aF[mt][1] = Ar[2 * mt + 1][2 * kk];
                aF[mt][2] = Ar[2 * mt][2 * kk + 1];
                aF[mt][3] = Ar[2 * mt + 1][2 * kk + 1];
            }
            #pragma unroll
            for (int nt = 0; nt < 8; nt++) {
                uint32_t b0 = fau(fb[(nt >> 1) * 4 + (nt & 1) * 2]);
                uint32_t b1 = fau(fb[(nt >> 1) * 4 + (nt & 1) * 2 + 1]);
                MMA_TF32(acc[0][nt], aF[0], b0, b1);
                MMA_TF32(acc[1][nt], aF[1], b0, b1);
            }
        }
    }

    float* ob = outp + ((size_t)b * HW + (size_t)(y0 + warp) * WID + x0) * 64;
    #pragma unroll
    for (int nt = 0; nt < 8; nt++) {
        int n = nt * 8 + 2 * tig;
        float bv0 = __ldg(bias + n), bv1 = __ldg(bias + n + 1);
        #pragma unroll
        for (int mt = 0; mt < 2; mt++)
            #pragma unroll
            for (int h = 0; h < 2; h++) {
                int x = qid + mt * 16 + h * 8;
                float v0 = rna_tf32(fmaxf(acc[mt][nt][h * 2 + 0] + bv0, 0.f));
                float v1 = rna_tf32(fmaxf(acc[mt][nt][h * 2 + 1] + bv1, 0.f));
                float2 o = {v0, v1};
                *(float2*)(ob + (size_t)x * 64 + n) = o;
            }
    }
}

// ---------------- conv3: 64->32 tf32 mma, vectorized, 3-tap weight chunks ----------------
// act smem ch-permuted p(ch)=(ch%8)*8+ch/8, AS=68.
__global__ void __launch_bounds__(512, 1) conv3_mma(
    const float* __restrict__ in, const float* __restrict__ wp,
    const float* __restrict__ bias, float* __restrict__ outp)
{
    constexpr int AS = 68;
    extern __shared__ float sm[];
    float* s_act = sm;              // 612*68
    float* s_w   = sm + 41616;      // 3*8*32*12 = 9216

    const int tid = threadIdx.x;
    const int b   = blockIdx.z;
    const int x0  = blockIdx.x * 32;
    const int y0  = blockIdx.y * 16;

    const float* inb = in + (size_t)b * HW * 64;
    for (int i = tid; i < 612 * 16; i += 512) {
        int px = i >> 4, j = i & 15;
        int yy = px / 34, xx = px - yy * 34;
        int gy = y0 - 1 + yy, gx = x0 - 1 + xx;
        float4 v = {0.f, 0.f, 0.f, 0.f};
        if ((unsigned)gy < HGT && (unsigned)gx < WID)
            v = *(const float4*)(inb + (size_t)(gy * WID + gx) * 64 + j * 4);
        float* sp = s_act + px * AS;
        const float* pv = (const float*)&v;
        #pragma unroll
        for (int e = 0; e < 4; e++) {
            int ch = 4 * j + e;
            sp[(ch & 7) * 8 + (ch >> 3)] = pv[e];
        }
    }

    const int warp = tid >> 5, lane = tid & 31;
    const int qid  = lane >> 2, tig = lane & 3;

    float acc[2][4][4];
    #pragma unroll
    for (int mt = 0; mt < 2; mt++)
        #pragma unroll
        for (int nt = 0; nt < 4; nt++)
            #pragma unroll
            for (int u = 0; u < 4; u++) acc[mt][nt][u] = 0.f;

    #pragma unroll 1
    for (int c = 0; c < 3; c++) {
        if (c) __syncthreads();
        for (int e = tid * 4; e < 9216; e += 2048)
            *(float4*)(s_w + e) = *(const float4*)(wp + c * 9216 + e);
        __syncthreads();

        #pragma unroll 1
        for (int j3 = 0; j3 < 3; j3++) {
            const int tap = c * 3 + j3;
            const int base_px = (warp + tap / 3) * 34 + tap % 3;
            uint32_t Ar[4][16];
            #pragma unroll
            for (int r = 0; r < 4; r++) {
                const float4* ap = (const float4*)(s_act + (base_px + qid + r * 8) * AS + tig * 8);
                float4 v0 = ap[0], v1 = ap[1], v2 = ap[8], v3 = ap[9];
                Ar[r][0] = fau(v0.x); Ar[r][1] = fau(v0.y); Ar[r][2] = fau(v0.z); Ar[r][3] = fau(v0.w);
                Ar[r][4] = fau(v1.x); Ar[r][5] = fau(v1.y); Ar[r][6] = fau(v1.z); Ar[r][7] = fau(v1.w);
                Ar[r][8] = fau(v2.x); Ar[r][9] = fau(v2.y); Ar[r][10] = fau(v2.z); Ar[r][11] = fau(v2.w);
                Ar[r][12] = fau(v3.x); Ar[r][13] = fau(v3.y); Ar[r][14] = fau(v3.z); Ar[r][15] = fau(v3.w);
            }
            #pragma unroll
            for (int kk = 0; kk < 8; kk++) {
                const float4* bp = (const float4*)(s_w + ((j3 * 8 + kk) * 32 + lane) * 12);
                float4 bf[2] = {bp[0], bp[1]};
                const float* fb = (const float*)bf;
                uint32_t aF[2][4];
                #pragma unroll
                for (int mt = 0; mt < 2; mt++) {
                    aF[mt][0] = Ar[2 * mt][kk];
                    aF[mt][1] = Ar[2 * mt + 1][kk];
                    aF[mt][2] = Ar[2 * mt][8 + kk];
                    aF[mt][3] = Ar[2 * mt + 1][8 + kk];
                }
                #pragma unroll
                for (int nt = 0; nt < 4; nt++) {
                    uint32_t b0 = fau(fb[(nt >> 1) * 4 + (nt & 1) * 2]);
                    uint32_t b1 = fau(fb[(nt >> 1) * 4 + (nt & 1) * 2 + 1]);
                    MMA_TF32(acc[0][nt], aF[0], b0, b1);
                    MMA_TF32(acc[1][nt], aF[1], b0, b1);
                }
            }
        }
    }

    float* ob = outp + ((size_t)b * HW + (size_t)(y0 + warp) * WID + x0) * 32;
    #pragma unroll
    for (int nt = 0; nt < 4; nt++) {
        int n = nt * 8 + 2 * tig;
        float bv0 = __ldg(bias + n), bv1 = __ldg(bias + n + 1);
        #pragma unroll
        for (int mt = 0; mt < 2; mt++)
            #pragma unroll
            for (int h = 0; h < 2; h++) {
                int x = qid + mt * 16 + h * 8;
                float v0 = fmaxf(acc[mt][nt][h * 2 + 0] + bv0, 0.f);
                float v1 = fmaxf(acc[mt][nt][h * 2 + 1] + bv1, 0.f);
                float2 o = {v0, v1};
                *(float2*)(ob + (size_t)x * 32 + n) = o;
            }
    }
}

// ---------------- conv4: 32->1 fp32 fused final (NHWC in) ----------------
__global__ void __launch_bounds__(256, 1) conv4_k(
    const float* __restrict__ a3, const float* __restrict__ w4,
    const float* __restrict__ b4, const float* __restrict__ sf,
    float* __restrict__ out)
{
    extern __shared__ float sm[];
    float* s_act = sm;                 // 18x18 px * 36
    float* s_w   = sm + 324 * 36;      // [tap][ci]
    const int tid = threadIdx.x;
    const int b = blockIdx.z, x0 = blockIdx.x * 16, y0 = blockIdx.y * 16;

    const float* inb = a3 + (size_t)b * HW * 32;
    for (int i = tid; i < 324 * 8; i += 256) {
        int px = i >> 3, j = i & 7;
        int yy = px / 18, xx = px - yy * 18;
        int gy = y0 - 1 + yy, gx = x0 - 1 + xx;
        float4 v = {0.f, 0.f, 0.f, 0.f};
        if ((unsigned)gy < HGT && (unsigned)gx < WID)
            v = *(const float4*)(inb + (size_t)(gy * WID + gx) * 32 + j * 4);
        *(float4*)(s_act + px * 36 + j * 4) = v;
    }
    for (int i = tid; i < 288; i += 256) s_w[(i % 9) * 32 + i / 9] = w4[i];
    __syncthreads();

    const int py = tid >> 4, px = tid & 15;
    float acc = 0.f;
    #pragma unroll
    for (int t = 0; t < 9; t++) {
        const float* sp = s_act + ((py + t / 3) * 18 + px + t % 3) * 36;
        const float* wpt = s_w + t * 32;
        #pragma unroll
        for (int c4 = 0; c4 < 8; c4++) {
            float4 xv = *(const float4*)(sp + c4 * 4);
            float4 wv = *(const float4*)(wpt + c4 * 4);
            acc = fmaf(xv.x, wv.x, acc);
            acc = fmaf(xv.y, wv.y, acc);
            acc = fmaf(xv.z, wv.z, acc);
            acc = fmaf(xv.w, wv.w, acc);
        }
    }
    float vh = (acc + b4[0]) * sf[0];
    size_t idx = (size_t)b * HW + (size_t)(y0 + py) * WID + (x0 + px);
    out[5 * (size_t)BHW + idx] = vh;
    out[idx] = out[(size_t)BHW + idx] + vh;
}

// ---------------- launch ----------------
extern "C" void kernel_launch(void* const* d_in, const int* in_sizes, int n_in,
                              void* d_out, int out_size)
{
    const float* inputs = (const float*)d_in[0];
    const float* H0     = (const float*)d_in[1];
    const float* C0     = (const float*)d_in[2];
    const float* c2     = (const float*)d_in[3];
    const float* sf     = (const float*)d_in[4];
    const float* w1     = (const float*)d_in[5];
    const float* b1     = (const float*)d_in[6];
    const float* w2     = (const float*)d_in[7];
    const float* b2     = (const float*)d_in[8];
    const float* w3     = (const float*)d_in[9];
    const float* b3     = (const float*)d_in[10];
    const float* w4     = (const float*)d_in[11];
    const float* b4     = (const float*)d_in[12];
    float* out = (float*)d_out;

    float *vs, *actA, *actB, *w2p, *w3p;
    cudaGetSymbolAddress((void**)&vs,   g_vs);
    cudaGetSymbolAddress((void**)&actA, g_actA);
    cudaGetSymbolAddress((void**)&actB, g_actB);
    cudaGetSymbolAddress((void**)&w2p,  g_w2p);
    cudaGetSymbolAddress((void**)&w3p,  g_w3p);

    const int SM2 = (22032 + 23040) * 4;   // 180288
    const int SM3 = (41616 + 9216) * 4;    // 203328
    const int SM4 = (324 * 36 + 288) * 4;  // 47808

    cudaFuncSetAttribute(conv2_mma, cudaFuncAttributeMaxDynamicSharedMemorySize, SM2);
    cudaFuncSetAttribute(conv3_mma, cudaFuncAttributeMaxDynamicSharedMemorySize, SM3);
    cudaFuncSetAttribute(conv4_k,   cudaFuncAttributeMaxDynamicSharedMemorySize, SM4);

    prep_kernel<<<BHW / 256, 256>>>(inputs, H0, C0, c2, sf, out, vs);
    w_pack_k<<<72, 256>>>(w2, w3, w2p, w3p);
    conv1_k<<<BHW / 256, 256>>>(vs, w1, b1, actA);

    dim3 tcg(WID / 32, HGT / 16, BATCH);  // (8, 16, 8)
    conv2_mma<<<tcg, 512, SM2>>>(actA, w2p, b2, actB);
    conv3_mma<<<tcg, 512, SM3>>>(actB, w3p, b3, actA);

    dim3 c4g(WID / 16, HGT / 16, BATCH);  // (16, 16, 8)
    conv4_k<<<c4g, 256, SM4>>>(actA, w4, b4, sf, out);
}

// round 9
// speedup vs baseline: 1.0558x; 1.0558x over previous
#include <cuda_runtime.h>
#include <cstdint>

#define WID 256
#define HGT 256
#define HW  65536
#define BATCH 8
#define BHW 524288

// ---------------- scratch ----------------
__device__ float g_vs[BHW];                        // V/sf
__device__ float g_actA[(size_t)BATCH * HW * 32];  // NHWC 32ch (conv1 out, conv3 out)
__device__ float g_actB[(size_t)BATCH * HW * 64];  // NHWC 64ch (conv2 out)
__device__ float g_w2p[9 * 4 * 32 * 20];           // conv2 weights lane-packed, tf32
__device__ float g_w3p[9 * 8 * 32 * 12];           // conv3 weights lane-packed, tf32

// ---------------- helpers ----------------
__device__ __forceinline__ float rna_tf32(float x) {
    uint32_t u;
    asm("cvt.rna.tf32.f32 %0, %1;" : "=r"(u) : "f"(x));
    return __uint_as_float(u);
}
__device__ __forceinline__ uint32_t fau(float x) { return __float_as_uint(x); }

#define MMA_TF32(d, a, b0, b1) \
    asm volatile("mma.sync.aligned.m16n8k8.row.col.f32.tf32.tf32.f32 " \
        "{%0,%1,%2,%3}, {%4,%5,%6,%7}, {%8,%9}, {%0,%1,%2,%3};" \
        : "+f"((d)[0]), "+f"((d)[1]), "+f"((d)[2]), "+f"((d)[3]) \
        : "r"((a)[0]), "r"((a)[1]), "r"((a)[2]), "r"((a)[3]), "r"(b0), "r"(b1))

// ---------------- prep ----------------
__global__ void __launch_bounds__(256) prep_kernel(
    const float* __restrict__ inp, const float* __restrict__ H0,
    const float* __restrict__ C0, const float* __restrict__ c2,
    const float* __restrict__ sf, float* __restrict__ out,
    float* __restrict__ vs)
{
    int idx = blockIdx.x * 256 + threadIdx.x;
    if (idx >= BHW) return;
    int b = idx >> 16, rem = idx & 65535, y = rem >> 8, x = rem & 255;

    float c  = inp[idx];
    float up = (y > 0)       ? inp[idx - WID] : 0.f;
    float dn = (y < HGT - 1) ? inp[idx + WID] : 0.f;
    float lf = (x > 0)       ? inp[idx - 1]   : 0.f;
    float rt = (x < WID - 1) ? inp[idx + 1]   : 0.f;
    float lap = up + dn + lf + rt - 4.f * c;

    float c0v = C0[(size_t)b * 2 * HW + rem];
    float Hv  = 2.f * c - c0v + c2[0] * lap;
    float V   = c - H0[idx];

    out[(size_t)BHW + idx]     = Hv;
    out[4 * (size_t)BHW + idx] = V;
    out[2 * (size_t)BHW + (size_t)b * 2 * HW + rem]      = c;
    out[2 * (size_t)BHW + (size_t)b * 2 * HW + HW + rem] = c0v;
    vs[idx] = V / sf[0];
}

// ---------------- weight pack (R8-validated): lane-fragment order, tf32 ----------------
__global__ void __launch_bounds__(256) w_pack_k(
    const float* __restrict__ w2, const float* __restrict__ w3,
    float* __restrict__ p2, float* __restrict__ p3)
{
    int idx = blockIdx.x * 256 + threadIdx.x;   // < 18432
    {   // conv2
        int e = idx & 3, j = (idx >> 2) & 3, lane = (idx >> 4) & 31;
        int kk = (idx >> 9) & 3, tap = idx >> 11;
        int qid = lane >> 2, tig = lane & 3;
        int nt = 2 * j + (e >> 1);
        int k = kk * 8 + tig + (e & 1) * 4;
        int n = nt * 8 + qid;
        p2[((tap * 4 + kk) * 32 + lane) * 20 + j * 4 + e] =
            rna_tf32(w2[((size_t)n * 32 + k) * 9 + tap]);
    }
    {   // conv3
        int e = idx & 3, j = (idx >> 2) & 1, lane = (idx >> 3) & 31;
        int kk = (idx >> 8) & 7, tap = idx >> 11;
        int qid = lane >> 2, tig = lane & 3;
        int nt = 2 * j + (e >> 1);
        int k = kk * 8 + tig + (e & 1) * 4;
        int n = nt * 8 + qid;
        p3[((tap * 8 + kk) * 32 + lane) * 12 + j * 4 + e] =
            rna_tf32(w3[((size_t)n * 64 + k) * 9 + tap]);
    }
}

// ---------------- conv1: 1->32 fp32, NHWC out, tf32-rounded ----------------
__global__ void __launch_bounds__(256) conv1_k(
    const float* __restrict__ vs, const float* __restrict__ w,
    const float* __restrict__ bb, float* __restrict__ outp)
{
    __shared__ float sw[288];
    __shared__ float sb[32];
    int tid = threadIdx.x;
    for (int i = tid; i < 288; i += 256) sw[i] = w[i];
    if (tid < 32) sb[tid] = bb[tid];
    __syncthreads();

    int pix = blockIdx.x * 256 + tid;
    int b = pix >> 16, rem = pix & 65535, y = rem >> 8, x = rem & 255;
    float xv[9];
    #pragma unroll
    for (int t = 0; t < 9; t++) {
        int gy = y + t / 3 - 1, gx = x + t % 3 - 1;
        xv[t] = ((unsigned)gy < HGT && (unsigned)gx < WID)
                    ? vs[(b << 16) + (gy << 8) + gx] : 0.f;
    }
    float* op = outp + (size_t)pix * 32;
    #pragma unroll
    for (int c4 = 0; c4 < 8; c4++) {
        float4 o;
        float* po = (float*)&o;
        #pragma unroll
        for (int u = 0; u < 4; u++) {
            int co = c4 * 4 + u;
            float acc = sb[co];
            #pragma unroll
            for (int t = 0; t < 9; t++) acc = fmaf(xv[t], sw[co * 9 + t], acc);
            po[u] = rna_tf32(fmaxf(acc, 0.f));
        }
        *(float4*)(op + c4 * 4) = o;
    }
}

// ---------------- conv2: 32->64 tf32 mma (R7 A-path + packed-B) ----------------
// CTA 512 thr, 16x32 tile. act plain NHWC padded, AS=36.
__global__ void __launch_bounds__(512, 1) conv2_mma(
    const float* __restrict__ in, const float* __restrict__ wp,
    const float* __restrict__ bias, float* __restrict__ outp)
{
    constexpr int AS = 36;
    extern __shared__ float sm[];
    float* s_act = sm;              // 612*36 = 22032
    float* s_w   = sm + 22032;      // 23040

    const int tid = threadIdx.x;
    const int b   = blockIdx.z;
    const int x0  = blockIdx.x * 32;
    const int y0  = blockIdx.y * 16;

    const float* inb = in + (size_t)b * HW * 32;
    for (int i = tid; i < 612 * 8; i += 512) {
        int px = i >> 3, j = i & 7;
        int yy = px / 34, xx = px - yy * 34;
        int gy = y0 - 1 + yy, gx = x0 - 1 + xx;
        float4 v = {0.f, 0.f, 0.f, 0.f};
        if ((unsigned)gy < HGT && (unsigned)gx < WID)
            v = *(const float4*)(inb + (size_t)(gy * WID + gx) * 32 + j * 4);
        *(float4*)(s_act + px * AS + j * 4) = v;
    }
    for (int e = tid * 4; e < 23040; e += 2048)
        *(float4*)(s_w + e) = *(const float4*)(wp + e);
    __syncthreads();

    const int warp = tid >> 5, lane = tid & 31;
    const int qid  = lane >> 2, tig = lane & 3;

    float acc[2][8][4];
    #pragma unroll
    for (int mt = 0; mt < 2; mt++)
        #pragma unroll
        for (int nt = 0; nt < 8; nt++)
            #pragma unroll
            for (int u = 0; u < 4; u++) acc[mt][nt][u] = 0.f;

    #pragma unroll 1
    for (int tap = 0; tap < 9; tap++) {
        const float* ab = s_act + ((warp + tap / 3) * 34 + tap % 3) * AS + tig;
        const float* wtp = s_w + (tap * 4 * 32 + lane) * 20;
        #pragma unroll
        for (int kk = 0; kk < 4; kk++) {
            uint32_t a[2][4];
            #pragma unroll
            for (int mt = 0; mt < 2; mt++) {
                const float* ap = ab + (qid + mt * 16) * AS + kk * 8;
                a[mt][0] = fau(ap[0]);          // A[qid][tig]
                a[mt][2] = fau(ap[4]);          // A[qid][tig+4]
                a[mt][1] = fau(ap[8 * AS]);     // A[qid+8][tig]
                a[mt][3] = fau(ap[8 * AS + 4]); // A[qid+8][tig+4]
            }
            const float4* bp = (const float4*)(wtp + kk * 32 * 20);
            float4 bf0 = bp[0], bf1 = bp[1], bf2 = bp[2], bf3 = bp[3];
            const float fb[16] = {bf0.x, bf0.y, bf0.z, bf0.w,
                                  bf1.x, bf1.y, bf1.z, bf1.w,
                                  bf2.x, bf2.y, bf2.z, bf2.w,
                                  bf3.x, bf3.y, bf3.z, bf3.w};
            #pragma unroll
            for (int nt = 0; nt < 8; nt++) {
                uint32_t b0 = fau(fb[(nt >> 1) * 4 + (nt & 1) * 2]);
                uint32_t b1 = fau(fb[(nt >> 1) * 4 + (nt & 1) * 2 + 1]);
                MMA_TF32(acc[0][nt], a[0], b0, b1);
                MMA_TF32(acc[1][nt], a[1], b0, b1);
            }
        }
    }

    float* ob = outp + ((size_t)b * HW + (size_t)(y0 + warp) * WID + x0) * 64;
    #pragma unroll
    for (int nt = 0; nt < 8; nt++) {
        int n = nt * 8 + 2 * tig;
        float bv0 = __ldg(bias + n), bv1 = __ldg(bias + n + 1);
        #pragma unroll
        for (int mt = 0; mt < 2; mt++)
            #pragma unroll
            for (int h = 0; h < 2; h++) {
                int x = qid + mt * 16 + h * 8;
                float v0 = rna_tf32(fmaxf(acc[mt][nt][h * 2 + 0] + bv0, 0.f));
                float v1 = rna_tf32(fmaxf(acc[mt][nt][h * 2 + 1] + bv1, 0.f));
                float2 o = {v0, v1};
                *(float2*)(ob + (size_t)x * 64 + n) = o;
            }
    }
}

// ---------------- conv3: 64->32 tf32 mma (R7 A-path + packed-B, 3-tap chunks) ----------------
__global__ void __launch_bounds__(512, 1) conv3_mma(
    const float* __restrict__ in, const float* __restrict__ wp,
    const float* __restrict__ bias, float* __restrict__ outp)
{
    constexpr int AS = 68;
    extern __shared__ float sm[];
    float* s_act = sm;              // 612*68 = 41616
    float* s_w   = sm + 41616;      // 3*8*32*12 = 9216

    const int tid = threadIdx.x;
    const int b   = blockIdx.z;
    const int x0  = blockIdx.x * 32;
    const int y0  = blockIdx.y * 16;

    const float* inb = in + (size_t)b * HW * 64;
    for (int i = tid; i < 612 * 16; i += 512) {
        int px = i >> 4, j = i & 15;
        int yy = px / 34, xx = px - yy * 34;
        int gy = y0 - 1 + yy, gx = x0 - 1 + xx;
        float4 v = {0.f, 0.f, 0.f, 0.f};
        if ((unsigned)gy < HGT && (unsigned)gx < WID)
            v = *(const float4*)(inb + (size_t)(gy * WID + gx) * 64 + j * 4);
        *(float4*)(s_act + px * AS + j * 4) = v;
    }

    const int warp = tid >> 5, lane = tid & 31;
    const int qid  = lane >> 2, tig = lane & 3;

    float acc[2][4][4];
    #pragma unroll
    for (int mt = 0; mt < 2; mt++)
        #pragma unroll
        for (int nt = 0; nt < 4; nt++)
            #pragma unroll
            for (int u = 0; u < 4; u++) acc[mt][nt][u] = 0.f;

    #pragma unroll 1
    for (int c = 0; c < 3; c++) {
        if (c) __syncthreads();
        for (int e = tid * 4; e < 9216; e += 2048)
            *(float4*)(s_w + e) = *(const float4*)(wp + c * 9216 + e);
        __syncthreads();

        #pragma unroll 1
        for (int j3 = 0; j3 < 3; j3++) {
            const int tap = c * 3 + j3;
            const float* ab = s_act + ((warp + tap / 3) * 34 + tap % 3) * AS + tig;
            const float* wtp = s_w + (j3 * 8 * 32 + lane) * 12;
            #pragma unroll
            for (int kk = 0; kk < 8; kk++) {
                uint32_t a[2][4];
                #pragma unroll
                for (int mt = 0; mt < 2; mt++) {
                    const float* ap = ab + (qid + mt * 16) * AS + kk * 8;
                    a[mt][0] = fau(ap[0]);
                    a[mt][2] = fau(ap[4]);
                    a[mt][1] = fau(ap[8 * AS]);
                    a[mt][3] = fau(ap[8 * AS + 4]);
                }
                const float4* bp = (const float4*)(wtp + kk * 32 * 12);
                float4 bf0 = bp[0], bf1 = bp[1];
                const float fb[8] = {bf0.x, bf0.y, bf0.z, bf0.w,
                                     bf1.x, bf1.y, bf1.z, bf1.w};
                #pragma unroll
                for (int nt = 0; nt < 4; nt++) {
                    uint32_t b0 = fau(fb[(nt >> 1) * 4 + (nt & 1) * 2]);
                    uint32_t b1 = fau(fb[(nt >> 1) * 4 + (nt & 1) * 2 + 1]);
                    MMA_TF32(acc[0][nt], a[0], b0, b1);
                    MMA_TF32(acc[1][nt], a[1], b0, b1);
                }
            }
        }
    }

    float* ob = outp + ((size_t)b * HW + (size_t)(y0 + warp) * WID + x0) * 32;
    #pragma unroll
    for (int nt = 0; nt < 4; nt++) {
        int n = nt * 8 + 2 * tig;
        float bv0 = __ldg(bias + n), bv1 = __ldg(bias + n + 1);
        #pragma unroll
        for (int mt = 0; mt < 2; mt++)
            #pragma unroll
            for (int h = 0; h < 2; h++) {
                int x = qid + mt * 16 + h * 8;
                float v0 = fmaxf(acc[mt][nt][h * 2 + 0] + bv0, 0.f);
                float v1 = fmaxf(acc[mt][nt][h * 2 + 1] + bv1, 0.f);
                float2 o = {v0, v1};
                *(float2*)(ob + (size_t)x * 32 + n) = o;
            }
    }
}

// ---------------- conv4: 32->1 fp32 fused final (NHWC in) ----------------
__global__ void __launch_bounds__(256, 1) conv4_k(
    const float* __restrict__ a3, const float* __restrict__ w4,
    const float* __restrict__ b4, const float* __restrict__ sf,
    float* __restrict__ out)
{
    extern __shared__ float sm[];
    float* s_act = sm;                 // 18x18 px * 36
    float* s_w   = sm + 324 * 36;      // [tap][ci]
    const int tid = threadIdx.x;
    const int b = blockIdx.z, x0 = blockIdx.x * 16, y0 = blockIdx.y * 16;

    const float* inb = a3 + (size_t)b * HW * 32;
    for (int i = tid; i < 324 * 8; i += 256) {
        int px = i >> 3, j = i & 7;
        int yy = px / 18, xx = px - yy * 18;
        int gy = y0 - 1 + yy, gx = x0 - 1 + xx;
        float4 v = {0.f, 0.f, 0.f, 0.f};
        if ((unsigned)gy < HGT && (unsigned)gx < WID)
            v = *(const float4*)(inb + (size_t)(gy * WID + gx) * 32 + j * 4);
        *(float4*)(s_act + px * 36 + j * 4) = v;
    }
    for (int i = tid; i < 288; i += 256) s_w[(i % 9) * 32 + i / 9] = w4[i];
    __syncthreads();

    const int py = tid >> 4, px = tid & 15;
    float acc = 0.f;
    #pragma unroll
    for (int t = 0; t < 9; t++) {
        const float* sp = s_act + ((py + t / 3) * 18 + px + t % 3) * 36;
        const float* wpt = s_w + t * 32;
        #pragma unroll
        for (int c4 = 0; c4 < 8; c4++) {
            float4 xv = *(const float4*)(sp + c4 * 4);
            float4 wv = *(const float4*)(wpt + c4 * 4);
            acc = fmaf(xv.x, wv.x, acc);
            acc = fmaf(xv.y, wv.y, acc);
            acc = fmaf(xv.z, wv.z, acc);
            acc = fmaf(xv.w, wv.w, acc);
        }
    }
    float vh = (acc + b4[0]) * sf[0];
    size_t idx = (size_t)b * HW + (size_t)(y0 + py) * WID + (x0 + px);
    out[5 * (size_t)BHW + idx] = vh;
    out[idx] = out[(size_t)BHW + idx] + vh;
}

// ---------------- launch ----------------
extern "C" void kernel_launch(void* const* d_in, const int* in_sizes, int n_in,
                              void* d_out, int out_size)
{
    const float* inputs = (const float*)d_in[0];
    const float* H0     = (const float*)d_in[1];
    const float* C0     = (const float*)d_in[2];
    const float* c2     = (const float*)d_in[3];
    const float* sf     = (const float*)d_in[4];
    const float* w1     = (const float*)d_in[5];
    const float* b1     = (const float*)d_in[6];
    const float* w2     = (const float*)d_in[7];
    const float* b2     = (const float*)d_in[8];
    const float* w3     = (const float*)d_in[9];
    const float* b3     = (const float*)d_in[10];
    const float* w4     = (const float*)d_in[11];
    const float* b4     = (const float*)d_in[12];
    float* out = (float*)d_out;

    float *vs, *actA, *actB, *w2p, *w3p;
    cudaGetSymbolAddress((void**)&vs,   g_vs);
    cudaGetSymbolAddress((void**)&actA, g_actA);
    cudaGetSymbolAddress((void**)&actB, g_actB);
    cudaGetSymbolAddress((void**)&w2p,  g_w2p);
    cudaGetSymbolAddress((void**)&w3p,  g_w3p);

    const int SM2 = (22032 + 23040) * 4;   // 180288
    const int SM3 = (41616 + 9216) * 4;    // 203328
    const int SM4 = (324 * 36 + 288) * 4;  // 47808

    cudaFuncSetAttribute(conv2_mma, cudaFuncAttributeMaxDynamicSharedMemorySize, SM2);
    cudaFuncSetAttribute(conv3_mma, cudaFuncAttributeMaxDynamicSharedMemorySize, SM3);
    cudaFuncSetAttribute(conv4_k,   cudaFuncAttributeMaxDynamicSharedMemorySize, SM4);

    prep_kernel<<<BHW / 256, 256>>>(inputs, H0, C0, c2, sf, out, vs);
    w_pack_k<<<72, 256>>>(w2, w3, w2p, w3p);
    conv1_k<<<BHW / 256, 256>>>(vs, w1, b1, actA);

    dim3 tcg(WID / 32, HGT / 16, BATCH);  // (8, 16, 8)
    conv2_mma<<<tcg, 512, SM2>>>(actA, w2p, b2, actB);
    conv3_mma<<<tcg, 512, SM3>>>(actB, w3p, b3, actA);

    dim3 c4g(WID / 16, HGT / 16, BATCH);  // (16, 16, 8)
    conv4_k<<<c4g, 256, SM4>>>(actA, w4, b4, sf, out);
}

// round 10
// speedup vs baseline: 1.1343x; 1.0744x over previous
#include <cuda_runtime.h>
#include <cstdint>

#define WID 256
#define HGT 256
#define HW  65536
#define BATCH 8
#define BHW 524288

// ---------------- scratch ----------------
__device__ float g_vs[BHW];                        // V/sf
__device__ float g_actA[(size_t)BATCH * HW * 32];  // NHWC 32ch (conv1 out, conv3 out)
__device__ float g_actB[(size_t)BATCH * HW * 64];  // NHWC 64ch (conv2 out)
__device__ float g_w2p[9 * 4 * 2 * 32 * 12];       // conv2 weights lane-packed (nhalf split)
__device__ float g_w3p[9 * 8 * 2 * 32 * 4];        // conv3 weights lane-packed (nhalf split)

// ---------------- helpers ----------------
__device__ __forceinline__ float rna_tf32(float x) {
    uint32_t u;
    asm("cvt.rna.tf32.f32 %0, %1;" : "=r"(u) : "f"(x));
    return __uint_as_float(u);
}
__device__ __forceinline__ uint32_t fau(float x) { return __float_as_uint(x); }

#define MMA_TF32(d, a, b0, b1) \
    asm volatile("mma.sync.aligned.m16n8k8.row.col.f32.tf32.tf32.f32 " \
        "{%0,%1,%2,%3}, {%4,%5,%6,%7}, {%8,%9}, {%0,%1,%2,%3};" \
        : "+f"((d)[0]), "+f"((d)[1]), "+f"((d)[2]), "+f"((d)[3]) \
        : "r"((a)[0]), "r"((a)[1]), "r"((a)[2]), "r"((a)[3]), "r"(b0), "r"(b1))

// ---------------- prep ----------------
__global__ void __launch_bounds__(256) prep_kernel(
    const float* __restrict__ inp, const float* __restrict__ H0,
    const float* __restrict__ C0, const float* __restrict__ c2,
    const float* __restrict__ sf, float* __restrict__ out,
    float* __restrict__ vs)
{
    int idx = blockIdx.x * 256 + threadIdx.x;
    if (idx >= BHW) return;
    int b = idx >> 16, rem = idx & 65535, y = rem >> 8, x = rem & 255;

    float c  = inp[idx];
    float up = (y > 0)       ? inp[idx - WID] : 0.f;
    float dn = (y < HGT - 1) ? inp[idx + WID] : 0.f;
    float lf = (x > 0)       ? inp[idx - 1]   : 0.f;
    float rt = (x < WID - 1) ? inp[idx + 1]   : 0.f;
    float lap = up + dn + lf + rt - 4.f * c;

    float c0v = C0[(size_t)b * 2 * HW + rem];
    float Hv  = 2.f * c - c0v + c2[0] * lap;
    float V   = c - H0[idx];

    out[(size_t)BHW + idx]     = Hv;
    out[4 * (size_t)BHW + idx] = V;
    out[2 * (size_t)BHW + (size_t)b * 2 * HW + rem]      = c;
    out[2 * (size_t)BHW + (size_t)b * 2 * HW + HW + rem] = c0v;
    vs[idx] = V / sf[0];
}

// ---------------- weight pack: per (tap,kk,nhalf,lane), tf32 ----------------
__global__ void __launch_bounds__(256) w_pack_k(
    const float* __restrict__ w2, const float* __restrict__ w3,
    float* __restrict__ p2, float* __restrict__ p3)
{
    int idx = blockIdx.x * 256 + threadIdx.x;   // < 18432
    {   // conv2: e in 0..7 -> nt_local = e>>1, ksel = e&1
        int e = idx & 7, lane = (idx >> 3) & 31;
        int nh = (idx >> 8) & 1, kk = (idx >> 9) & 3, tap = idx >> 11;
        int qid = lane >> 2, tig = lane & 3;
        int n = (nh * 4 + (e >> 1)) * 8 + qid;
        int k = kk * 8 + tig + (e & 1) * 4;
        p2[(((tap * 4 + kk) * 2 + nh) * 32 + lane) * 12 + e] =
            rna_tf32(w2[((size_t)n * 32 + k) * 9 + tap]);
    }
    {   // conv3: e in 0..3 -> nt_local = e>>1, ksel = e&1
        int e = idx & 3, lane = (idx >> 2) & 31;
        int nh = (idx >> 7) & 1, kk = (idx >> 8) & 7, tap = idx >> 11;
        int qid = lane >> 2, tig = lane & 3;
        int n = (nh * 2 + (e >> 1)) * 8 + qid;
        int k = kk * 8 + tig + (e & 1) * 4;
        p3[(((tap * 8 + kk) * 2 + nh) * 32 + lane) * 4 + e] =
            rna_tf32(w3[((size_t)n * 64 + k) * 9 + tap]);
    }
}

// ---------------- conv1: 1->32 fp32, NHWC out, tf32-rounded ----------------
__global__ void __launch_bounds__(256) conv1_k(
    const float* __restrict__ vs, const float* __restrict__ w,
    const float* __restrict__ bb, float* __restrict__ outp)
{
    __shared__ float sw[288];
    __shared__ float sb[32];
    int tid = threadIdx.x;
    for (int i = tid; i < 288; i += 256) sw[i] = w[i];
    if (tid < 32) sb[tid] = bb[tid];
    __syncthreads();

    int pix = blockIdx.x * 256 + tid;
    int b = pix >> 16, rem = pix & 65535, y = rem >> 8, x = rem & 255;
    float xv[9];
    #pragma unroll
    for (int t = 0; t < 9; t++) {
        int gy = y + t / 3 - 1, gx = x + t % 3 - 1;
        xv[t] = ((unsigned)gy < HGT && (unsigned)gx < WID)
                    ? vs[(b << 16) + (gy << 8) + gx] : 0.f;
    }
    float* op = outp + (size_t)pix * 32;
    #pragma unroll
    for (int c4 = 0; c4 < 8; c4++) {
        float4 o;
        float* po = (float*)&o;
        #pragma unroll
        for (int u = 0; u < 4; u++) {
            int co = c4 * 4 + u;
            float acc = sb[co];
            #pragma unroll
            for (int t = 0; t < 9; t++) acc = fmaf(xv[t], sw[co * 9 + t], acc);
            po[u] = rna_tf32(fmaxf(acc, 0.f));
        }
        *(float4*)(op + c4 * 4) = o;
    }
}

// ---------------- conv2: 32->64 tf32 mma, 1024 thr, n-split warps ----------------
// tile 16x32; warp w: row = w>>1, nhalf = w&1 (n offset nhalf*32, 4 n-tiles)
__global__ void __launch_bounds__(1024, 1) conv2_mma(
    const float* __restrict__ in, const float* __restrict__ wp,
    const float* __restrict__ bias, float* __restrict__ outp)
{
    constexpr int AS = 36;
    extern __shared__ float sm[];
    float* s_act = sm;              // 612*36 = 22032
    float* s_w   = sm + 22032;      // 9*4*2*32*12 = 27648

    const int tid = threadIdx.x;
    const int b   = blockIdx.z;
    const int x0  = blockIdx.x * 32;
    const int y0  = blockIdx.y * 16;

    const float* inb = in + (size_t)b * HW * 32;
    for (int i = tid; i < 612 * 8; i += 1024) {
        int px = i >> 3, j = i & 7;
        int yy = px / 34, xx = px - yy * 34;
        int gy = y0 - 1 + yy, gx = x0 - 1 + xx;
        float4 v = {0.f, 0.f, 0.f, 0.f};
        if ((unsigned)gy < HGT && (unsigned)gx < WID)
            v = *(const float4*)(inb + (size_t)(gy * WID + gx) * 32 + j * 4);
        *(float4*)(s_act + px * AS + j * 4) = v;
    }
    for (int e = tid * 4; e < 27648; e += 4096)
        *(float4*)(s_w + e) = *(const float4*)(wp + e);
    __syncthreads();

    const int warp = tid >> 5, lane = tid & 31;
    const int row = warp >> 1, nh = warp & 1;
    const int qid = lane >> 2, tig = lane & 3;

    float acc[2][4][4];
    #pragma unroll
    for (int mt = 0; mt < 2; mt++)
        #pragma unroll
        for (int nt = 0; nt < 4; nt++)
            #pragma unroll
            for (int u = 0; u < 4; u++) acc[mt][nt][u] = 0.f;

    #pragma unroll 1
    for (int tap = 0; tap < 9; tap++) {
        const float* ab = s_act + ((row + tap / 3) * 34 + tap % 3) * AS + tig;
        const float* wtp = s_w + (((tap * 4) * 2 + nh) * 32 + lane) * 12;
        #pragma unroll
        for (int kk = 0; kk < 4; kk++) {
            uint32_t a[2][4];
            #pragma unroll
            for (int mt = 0; mt < 2; mt++) {
                const float* ap = ab + (qid + mt * 16) * AS + kk * 8;
                a[mt][0] = fau(ap[0]);          // A[qid][tig]
                a[mt][2] = fau(ap[4]);          // A[qid][tig+4]
                a[mt][1] = fau(ap[8 * AS]);     // A[qid+8][tig]
                a[mt][3] = fau(ap[8 * AS + 4]); // A[qid+8][tig+4]
            }
            const float4* bp = (const float4*)(wtp + kk * 2 * 32 * 12);
            float4 bf0 = bp[0], bf1 = bp[1];
            const float fb[8] = {bf0.x, bf0.y, bf0.z, bf0.w,
                                 bf1.x, bf1.y, bf1.z, bf1.w};
            #pragma unroll
            for (int nt = 0; nt < 4; nt++) {
                uint32_t b0 = fau(fb[nt * 2]);
                uint32_t b1 = fau(fb[nt * 2 + 1]);
                MMA_TF32(acc[0][nt], a[0], b0, b1);
                MMA_TF32(acc[1][nt], a[1], b0, b1);
            }
        }
    }

    float* ob = outp + ((size_t)b * HW + (size_t)(y0 + row) * WID + x0) * 64;
    #pragma unroll
    for (int nt = 0; nt < 4; nt++) {
        int n = nh * 32 + nt * 8 + 2 * tig;
        float bv0 = __ldg(bias + n), bv1 = __ldg(bias + n + 1);
        #pragma unroll
        for (int mt = 0; mt < 2; mt++)
            #pragma unroll
            for (int h = 0; h < 2; h++) {
                int x = qid + mt * 16 + h * 8;
                float v0 = rna_tf32(fmaxf(acc[mt][nt][h * 2 + 0] + bv0, 0.f));
                float v1 = rna_tf32(fmaxf(acc[mt][nt][h * 2 + 1] + bv1, 0.f));
                float2 o = {v0, v1};
                *(float2*)(ob + (size_t)x * 64 + n) = o;
            }
    }
}

// ---------------- conv3: 64->32 tf32 mma, 1024 thr, n-split warps, 3-tap chunks ----------------
__global__ void __launch_bounds__(1024, 1) conv3_mma(
    const float* __restrict__ in, const float* __restrict__ wp,
    const float* __restrict__ bias, float* __restrict__ outp)
{
    constexpr int AS = 68;
    extern __shared__ float sm[];
    float* s_act = sm;              // 612*68 = 41616
    float* s_w   = sm + 41616;      // 3*8*2*32*4 = 6144

    const int tid = threadIdx.x;
    const int b   = blockIdx.z;
    const int x0  = blockIdx.x * 32;
    const int y0  = blockIdx.y * 16;

    const float* inb = in + (size_t)b * HW * 64;
    for (int i = tid; i < 612 * 16; i += 1024) {
        int px = i >> 4, j = i & 15;
        int yy = px / 34, xx = px - yy * 34;
        int gy = y0 - 1 + yy, gx = x0 - 1 + xx;
        float4 v = {0.f, 0.f, 0.f, 0.f};
        if ((unsigned)gy < HGT && (unsigned)gx < WID)
            v = *(const float4*)(inb + (size_t)(gy * WID + gx) * 64 + j * 4);
        *(float4*)(s_act + px * AS + j * 4) = v;
    }

    const int warp = tid >> 5, lane = tid & 31;
    const int row = warp >> 1, nh = warp & 1;
    const int qid = lane >> 2, tig = lane & 3;

    float acc[2][2][4];
    #pragma unroll
    for (int mt = 0; mt < 2; mt++)
        #pragma unroll
        for (int nt = 0; nt < 2; nt++)
            #pragma unroll
            for (int u = 0; u < 4; u++) acc[mt][nt][u] = 0.f;

    #pragma unroll 1
    for (int c = 0; c < 3; c++) {
        if (c) __syncthreads();
        for (int e = tid * 4; e < 6144; e += 4096)
            *(float4*)(s_w + e) = *(const float4*)(wp + c * 6144 + e);
        __syncthreads();

        #pragma unroll 1
        for (int j3 = 0; j3 < 3; j3++) {
            const int tap = c * 3 + j3;
            const float* ab = s_act + ((row + tap / 3) * 34 + tap % 3) * AS + tig;
            const float* wtp = s_w + (((j3 * 8) * 2 + nh) * 32 + lane) * 4;
            #pragma unroll
            for (int kk = 0; kk < 8; kk++) {
                uint32_t a[2][4];
                #pragma unroll
                for (int mt = 0; mt < 2; mt++) {
                    const float* ap = ab + (qid + mt * 16) * AS + kk * 8;
                    a[mt][0] = fau(ap[0]);
                    a[mt][2] = fau(ap[4]);
                    a[mt][1] = fau(ap[8 * AS]);
                    a[mt][3] = fau(ap[8 * AS + 4]);
                }
                float4 bf = *(const float4*)(wtp + kk * 2 * 32 * 4);
                MMA_TF32(acc[0][0], a[0], fau(bf.x), fau(bf.y));
                MMA_TF32(acc[1][0], a[1], fau(bf.x), fau(bf.y));
                MMA_TF32(acc[0][1], a[0], fau(bf.z), fau(bf.w));
                MMA_TF32(acc[1][1], a[1], fau(bf.z), fau(bf.w));
            }
        }
    }

    float* ob = outp + ((size_t)b * HW + (size_t)(y0 + row) * WID + x0) * 32;
    #pragma unroll
    for (int nt = 0; nt < 2; nt++) {
        int n = nh * 16 + nt * 8 + 2 * tig;
        float bv0 = __ldg(bias + n), bv1 = __ldg(bias + n + 1);
        #pragma unroll
        for (int mt = 0; mt < 2; mt++)
            #pragma unroll
            for (int h = 0; h < 2; h++) {
                int x = qid + mt * 16 + h * 8;
                float v0 = fmaxf(acc[mt][nt][h * 2 + 0] + bv0, 0.f);
                float v1 = fmaxf(acc[mt][nt][h * 2 + 1] + bv1, 0.f);
                float2 o = {v0, v1};
                *(float2*)(ob + (size_t)x * 32 + n) = o;
            }
    }
}

// ---------------- conv4: 32->1 fp32 fused final (NHWC in) ----------------
__global__ void __launch_bounds__(256, 1) conv4_k(
    const float* __restrict__ a3, const float* __restrict__ w4,
    const float* __restrict__ b4, const float* __restrict__ sf,
    float* __restrict__ out)
{
    extern __shared__ float sm[];
    float* s_act = sm;                 // 18x18 px * 36
    float* s_w   = sm + 324 * 36;      // [tap][ci]
    const int tid = threadIdx.x;
    const int b = blockIdx.z, x0 = blockIdx.x * 16, y0 = blockIdx.y * 16;

    const float* inb = a3 + (size_t)b * HW * 32;
    for (int i = tid; i < 324 * 8; i += 256) {
        int px = i >> 3, j = i & 7;
        int yy = px / 18, xx = px - yy * 18;
        int gy = y0 - 1 + yy, gx = x0 - 1 + xx;
        float4 v = {0.f, 0.f, 0.f, 0.f};
        if ((unsigned)gy < HGT && (unsigned)gx < WID)
            v = *(const float4*)(inb + (size_t)(gy * WID + gx) * 32 + j * 4);
        *(float4*)(s_act + px * 36 + j * 4) = v;
    }
    for (int i = tid; i < 288; i += 256) s_w[(i % 9) * 32 + i / 9] = w4[i];
    __syncthreads();

    const int py = tid >> 4, px = tid & 15;
    float acc = 0.f;
    #pragma unroll
    for (int t = 0; t < 9; t++) {
        const float* sp = s_act + ((py + t / 3) * 18 + px + t % 3) * 36;
        const float* wpt = s_w + t * 32;
        #pragma unroll
        for (int c4 = 0; c4 < 8; c4++) {
            float4 xv = *(const float4*)(sp + c4 * 4);
            float4 wv = *(const float4*)(wpt + c4 * 4);
            acc = fmaf(xv.x, wv.x, acc);
            acc = fmaf(xv.y, wv.y, acc);
            acc = fmaf(xv.z, wv.z, acc);
            acc = fmaf(xv.w, wv.w, acc);
        }
    }
    float vh = (acc + b4[0]) * sf[0];
    size_t idx = (size_t)b * HW + (size_t)(y0 + py) * WID + (x0 + px);
    out[5 * (size_t)BHW + idx] = vh;
    out[idx] = out[(size_t)BHW + idx] + vh;
}

// ---------------- launch ----------------
extern "C" void kernel_launch(void* const* d_in, const int* in_sizes, int n_in,
                              void* d_out, int out_size)
{
    const float* inputs = (const float*)d_in[0];
    const float* H0     = (const float*)d_in[1];
    const float* C0     = (const float*)d_in[2];
    const float* c2     = (const float*)d_in[3];
    const float* sf     = (const float*)d_in[4];
    const float* w1     = (const float*)d_in[5];
    const float* b1     = (const float*)d_in[6];
    const float* w2     = (const float*)d_in[7];
    const float* b2     = (const float*)d_in[8];
    const float* w3     = (const float*)d_in[9];
    const float* b3     = (const float*)d_in[10];
    const float* w4     = (const float*)d_in[11];
    const float* b4     = (const float*)d_in[12];
    float* out = (float*)d_out;

    float *vs, *actA, *actB, *w2p, *w3p;
    cudaGetSymbolAddress((void**)&vs,   g_vs);
    cudaGetSymbolAddress((void**)&actA, g_actA);
    cudaGetSymbolAddress((void**)&actB, g_actB);
    cudaGetSymbolAddress((void**)&w2p,  g_w2p);
    cudaGetSymbolAddress((void**)&w3p,  g_w3p);

    const int SM2 = (22032 + 27648) * 4;   // 198720
    const int SM3 = (41616 + 6144) * 4;    // 191040
    const int SM4 = (324 * 36 + 288) * 4;  // 47808

    cudaFuncSetAttribute(conv2_mma, cudaFuncAttributeMaxDynamicSharedMemorySize, SM2);
    cudaFuncSetAttribute(conv3_mma, cudaFuncAttributeMaxDynamicSharedMemorySize, SM3);
    cudaFuncSetAttribute(conv4_k,   cudaFuncAttributeMaxDynamicSharedMemorySize, SM4);

    prep_kernel<<<BHW / 256, 256>>>(inputs, H0, C0, c2, sf, out, vs);
    w_pack_k<<<72, 256>>>(w2, w3, w2p, w3p);
    conv1_k<<<BHW / 256, 256>>>(vs, w1, b1, actA);

    dim3 tcg(WID / 32, HGT / 16, BATCH);  // (8, 16, 8)
    conv2_mma<<<tcg, 1024, SM2>>>(actA, w2p, b2, actB);
    conv3_mma<<<tcg, 1024, SM3>>>(actB, w3p, b3, actA);

    dim3 c4g(WID / 16, HGT / 16, BATCH);  // (16, 16, 8)
    conv4_k<<<c4g, 256, SM4>>>(actA, w4, b4, sf, out);
}